// round 1
// baseline (speedup 1.0000x reference)
#include <cuda_runtime.h>
#include <math.h>

// Problem constants
constexpr int BATCH = 4;
constexpr int SEQ   = 4096;
constexpr int HID   = 1024;
constexpr int NH    = 16;
constexpr int QK    = 64;
constexpr int VD    = 64;
constexpr int KS    = 4;
constexpr int RED   = 128;   // HID/8
constexpr int MTOK  = BATCH * SEQ;  // 16384

// Scratch (static device arrays; no runtime allocation)
__device__ float g_Q   [(size_t)MTOK * HID];      // raw Q (pre-rope)
__device__ float g_V   [(size_t)MTOK * HID];      // V
__device__ float g_H1  [(size_t)MTOK * RED];      // x @ kg_w1 (pre-silu)
__device__ float g_u   [(size_t)BATCH * NH * SEQ];
__device__ float g_v   [(size_t)BATCH * NH * SEQ];
__device__ float g_k4  [(size_t)BATCH * NH * SEQ * KS];
__device__ float g_scan[(size_t)MTOK * HID];      // scan outputs [tok][h*VD+d]

// ---------------------------------------------------------------------------
// SGEMM: C[M,N] = A[M,K] @ B[K,N] + bias[N]   (all row-major, fp32)
// 128x128 block tile, BK=16, 256 threads, 8x8 per-thread tile.
// Requires M%128==0, N%128==0, K%16==0 (true for all our shapes).
// ---------------------------------------------------------------------------
__global__ __launch_bounds__(256) void sgemm_kernel(
    const float* __restrict__ A, const float* __restrict__ B,
    const float* __restrict__ bias, float* __restrict__ C,
    int M, int N, int K)
{
    constexpr int BM = 128, BN = 128, BK = 16;
    __shared__ float As[BK][BM];     // transposed A tile
    __shared__ float Bs[BK][BN];

    const int tid = threadIdx.x;
    const int bm  = blockIdx.y * BM;
    const int bn  = blockIdx.x * BN;
    const int tx  = tid & 15;        // 16 col groups
    const int ty  = tid >> 4;        // 16 row groups

    float acc[8][8] = {};

    const float* Ab = A + (size_t)bm * K;
    const float* Bb = B + bn;

    for (int k0 = 0; k0 < K; k0 += BK) {
        // Load A tile: 128 rows x 16 cols = 512 float4, 2 per thread
        #pragma unroll
        for (int p = 0; p < 2; p++) {
            int f   = tid + p * 256;
            int row = f >> 2;
            int c4  = (f & 3) << 2;
            float4 va = *reinterpret_cast<const float4*>(Ab + (size_t)row * K + k0 + c4);
            As[c4 + 0][row] = va.x;
            As[c4 + 1][row] = va.y;
            As[c4 + 2][row] = va.z;
            As[c4 + 3][row] = va.w;
        }
        // Load B tile: 16 rows x 128 cols = 512 float4, 2 per thread
        #pragma unroll
        for (int p = 0; p < 2; p++) {
            int f   = tid + p * 256;
            int row = f >> 5;
            int c4  = (f & 31) << 2;
            *reinterpret_cast<float4*>(&Bs[row][c4]) =
                *reinterpret_cast<const float4*>(Bb + (size_t)(k0 + row) * N + c4);
        }
        __syncthreads();

        #pragma unroll
        for (int k = 0; k < BK; k++) {
            float a[8], br[8];
            #pragma unroll
            for (int i = 0; i < 8; i++) a[i]  = As[k][ty * 8 + i];
            #pragma unroll
            for (int j = 0; j < 8; j++) br[j] = Bs[k][tx * 8 + j];
            #pragma unroll
            for (int i = 0; i < 8; i++)
                #pragma unroll
                for (int j = 0; j < 8; j++)
                    acc[i][j] = fmaf(a[i], br[j], acc[i][j]);
        }
        __syncthreads();
    }

    float bs[8];
    #pragma unroll
    for (int j = 0; j < 8; j++) bs[j] = bias[bn + tx * 8 + j];

    #pragma unroll
    for (int i = 0; i < 8; i++) {
        float* Crow = C + (size_t)(bm + ty * 8 + i) * N + bn + tx * 8;
        float4 o0 = make_float4(acc[i][0] + bs[0], acc[i][1] + bs[1],
                                acc[i][2] + bs[2], acc[i][3] + bs[3]);
        float4 o1 = make_float4(acc[i][4] + bs[4], acc[i][5] + bs[5],
                                acc[i][6] + bs[6], acc[i][7] + bs[7]);
        *reinterpret_cast<float4*>(Crow)     = o0;
        *reinterpret_cast<float4*>(Crow + 4) = o1;
    }
}

// ---------------------------------------------------------------------------
// Mid kernel: per (token, head):
//   RoPE(Q) -> gates u,v = sigmoid(Qr @ gate_w + gate_b)
//   kernels = silu(H1) @ kg_w2 + kg_b2
// Block = 256 threads = 16 tokens x 16 heads.
// Outputs in [B][NH][SEQ] layout for the scan kernel.
// ---------------------------------------------------------------------------
__global__ __launch_bounds__(256) void mid_kernel(
    const float* __restrict__ kg_w2, const float* __restrict__ kg_b2,
    const float* __restrict__ gate_w, const float* __restrict__ gate_b)
{
    __shared__ float h1s[16][RED];
    const int tid = threadIdx.x;
    const int tokBase = blockIdx.x * 16;

    // cooperative load + silu of H1 rows
    for (int i = tid; i < 16 * RED; i += 256) {
        int tk = i / RED, c = i % RED;
        float val = g_H1[(size_t)(tokBase + tk) * RED + c];
        h1s[tk][c] = val / (1.f + expf(-val));
    }
    __syncthreads();

    const int tl = tid >> 4;        // local token 0..15
    const int h  = tid & 15;        // head
    const int gtok = tokBase + tl;
    const int b = gtok >> 12;       // SEQ = 4096 = 2^12
    const int t = gtok & (SEQ - 1);

    // Load this head's Q row (64 floats)
    float q[QK];
    const float4* qp = reinterpret_cast<const float4*>(g_Q + (size_t)gtok * HID + h * QK);
    #pragma unroll
    for (int j = 0; j < QK / 4; j++) {
        float4 f = qp[j];
        q[4*j] = f.x; q[4*j+1] = f.y; q[4*j+2] = f.z; q[4*j+3] = f.w;
    }

    // RoPE: half = 32, freq_j = 10000^(-j/16)
    const float LOGC = 9.210340371976184f / 16.0f;  // ln(10000)/16
    #pragma unroll
    for (int j = 0; j < 32; j++) {
        float freq = expf(-LOGC * (float)j);
        float s, c;
        sincosf((float)t * freq, &s, &c);
        float a = q[j], bq = q[j + 32];
        q[j]      = a * c - bq * s;
        q[j + 32] = a * s + bq * c;
    }

    // Gates
    float du = gate_b[0], dv = gate_b[1];
    #pragma unroll
    for (int j = 0; j < QK; j++) {
        du = fmaf(q[j], gate_w[2 * j],     du);
        dv = fmaf(q[j], gate_w[2 * j + 1], dv);
    }
    float uu = 1.f / (1.f + expf(-du));
    float vv = 1.f / (1.f + expf(-dv));

    const size_t bhT = ((size_t)b * NH + h) * SEQ + t;
    g_u[bhT] = uu;
    g_v[bhT] = vv;

    // kernels[h][k] = silu(H1) . kg_w2[:, h*4+k] + kg_b2[h*4+k]
    float ak[KS];
    #pragma unroll
    for (int k = 0; k < KS; k++) ak[k] = kg_b2[h * KS + k];
    for (int r = 0; r < RED; r++) {
        float hv = h1s[tl][r];
        float4 w = *reinterpret_cast<const float4*>(kg_w2 + (size_t)r * (NH * KS) + h * KS);
        ak[0] = fmaf(hv, w.x, ak[0]);
        ak[1] = fmaf(hv, w.y, ak[1]);
        ak[2] = fmaf(hv, w.z, ak[2]);
        ak[3] = fmaf(hv, w.w, ak[3]);
    }
    #pragma unroll
    for (int k = 0; k < KS; k++) g_k4[bhT * KS + k] = ak[k];
}

// ---------------------------------------------------------------------------
// Scan kernel: one block per (b, h), 64 threads (d).
// Fuses the depth-4 causal conv (Vmix) via a register ring over V,
// then the linear recurrence ctx = ctx*u + vmix*v.
// ---------------------------------------------------------------------------
__global__ __launch_bounds__(64) void scan_kernel()
{
    const int bh = blockIdx.x;
    const int b  = bh / NH;
    const int h  = bh % NH;
    const int d  = threadIdx.x;

    const float* up = g_u  + (size_t)bh * SEQ;
    const float* vp = g_v  + (size_t)bh * SEQ;
    const float* kp = g_k4 + (size_t)bh * SEQ * KS;

    const size_t base = ((size_t)b * SEQ * NH + h) * VD + d;
    const float* Vp = g_V    + base;
    float*       Op = g_scan + base;
    constexpr int STR = NH * VD;   // 1024 floats between consecutive t

    __shared__ float su[128], sv[128], sk[128 * KS];

    float ctx = 0.f, r0 = 0.f, r1 = 0.f, r2 = 0.f;

    for (int t0 = 0; t0 < SEQ; t0 += 128) {
        __syncthreads();
        for (int i = d; i < 128; i += 64) { su[i] = up[t0 + i]; sv[i] = vp[t0 + i]; }
        for (int i = d; i < 128 * KS; i += 64) sk[i] = kp[(size_t)t0 * KS + i];
        __syncthreads();

        #pragma unroll 4
        for (int i = 0; i < 128; i++) {
            float cur = Vp[(size_t)(t0 + i) * STR];
            // vmix = k0*V[t-3] + k1*V[t-2] + k2*V[t-1] + k3*V[t]
            float vm = fmaf(sk[4*i], r0,
                       fmaf(sk[4*i+1], r1,
                       fmaf(sk[4*i+2], r2, sk[4*i+3] * cur)));
            ctx = fmaf(ctx, su[i], vm * sv[i]);
            Op[(size_t)(t0 + i) * STR] = ctx;
            r0 = r1; r1 = r2; r2 = cur;
        }
    }
}

// ---------------------------------------------------------------------------
// Launch
// ---------------------------------------------------------------------------
extern "C" void kernel_launch(void* const* d_in, const int* in_sizes, int n_in,
                              void* d_out, int out_size)
{
    const float* x      = (const float*)d_in[0];
    const float* W_q    = (const float*)d_in[1];
    const float* b_q    = (const float*)d_in[2];
    // d_in[3], d_in[4] = W_k, b_k : K is dead in the reference — skipped.
    const float* W_v    = (const float*)d_in[5];
    const float* b_v    = (const float*)d_in[6];
    const float* kg_w1  = (const float*)d_in[7];
    const float* kg_b1  = (const float*)d_in[8];
    const float* kg_w2  = (const float*)d_in[9];
    const float* kg_b2  = (const float*)d_in[10];
    const float* gate_w = (const float*)d_in[11];
    const float* gate_b = (const float*)d_in[12];
    const float* W_out  = (const float*)d_in[13];
    const float* b_out  = (const float*)d_in[14];
    float* out = (float*)d_out;

    static float *pQ = nullptr, *pV = nullptr, *pH1 = nullptr, *pScan = nullptr;
    if (!pQ) {
        cudaGetSymbolAddress((void**)&pQ,    g_Q);
        cudaGetSymbolAddress((void**)&pV,    g_V);
        cudaGetSymbolAddress((void**)&pH1,   g_H1);
        cudaGetSymbolAddress((void**)&pScan, g_scan);
    }

    dim3 blk(256);
    // Q = x @ W_q + b_q
    sgemm_kernel<<<dim3(HID / 128, MTOK / 128), blk>>>(x, W_q, b_q, pQ, MTOK, HID, HID);
    // V = x @ W_v + b_v
    sgemm_kernel<<<dim3(HID / 128, MTOK / 128), blk>>>(x, W_v, b_v, pV, MTOK, HID, HID);
    // H1 = x @ kg_w1 + kg_b1
    sgemm_kernel<<<dim3(RED / 128, MTOK / 128), blk>>>(x, kg_w1, kg_b1, pH1, MTOK, RED, HID);
    // RoPE + gates + conv kernels
    mid_kernel<<<MTOK / 16, 256>>>(kg_w2, kg_b2, gate_w, gate_b);
    // Vmix conv + linear scan
    scan_kernel<<<BATCH * NH, 64>>>();
    // out = scan @ W_out + b_out
    sgemm_kernel<<<dim3(HID / 128, MTOK / 128), blk>>>(pScan, W_out, b_out, out, MTOK, HID, HID);
}

// round 2
// speedup vs baseline: 1.5999x; 1.5999x over previous
#include <cuda_runtime.h>
#include <math.h>
#include <stdint.h>

// Problem constants
constexpr int BATCH = 4;
constexpr int SEQ   = 4096;
constexpr int HID   = 1024;
constexpr int NH    = 16;
constexpr int QK    = 64;
constexpr int VD    = 64;
constexpr int KS    = 4;
constexpr int RED   = 128;   // HID/8
constexpr int MTOK  = BATCH * SEQ;  // 16384

// Scratch (static device arrays; no runtime allocation)
__device__ float g_Q   [(size_t)MTOK * HID];
__device__ float g_V   [(size_t)MTOK * HID];
__device__ float g_H1  [(size_t)MTOK * RED];
__device__ float g_u   [(size_t)BATCH * NH * SEQ];
__device__ float g_v   [(size_t)BATCH * NH * SEQ];
__device__ float g_k4  [(size_t)BATCH * NH * SEQ * KS];
__device__ float g_scan[(size_t)MTOK * HID];

// ---------------------------------------------------------------------------
// TF32 tensor-core GEMM: C[M,N] = A[M,K] @ B[K,N] + bias[N]  (row-major fp32)
// 128x128 CTA tile, BK=16, 256 threads (8 warps, 4x2), warp tile 32x64,
// mma.sync.m16n8k8 tf32, cp.async double-buffered smem.
// Requires M%128==0, N%128==0, K%16==0.
// ---------------------------------------------------------------------------
__device__ __forceinline__ void cp16(uint32_t dst, const void* src) {
    asm volatile("cp.async.cg.shared.global [%0], [%1], 16;\n" :: "r"(dst), "l"(src));
}
__device__ __forceinline__ uint32_t f2tf32(float f) {
    uint32_t u;
    asm("cvt.rna.tf32.f32 %0, %1;" : "=r"(u) : "f"(f));
    return u;
}

__global__ __launch_bounds__(256) void gemm_tf32(
    const float* __restrict__ A, const float* __restrict__ B,
    const float* __restrict__ bias, float* __restrict__ C,
    int M, int N, int K)
{
    constexpr int BM = 128, BN = 128, BK = 16;
    constexpr int ASR = 20;    // A smem row stride (16 + 4 pad) -> conflict-free frag loads
    constexpr int BSR = 136;   // B smem row stride (128 + 8 pad) -> conflict-free frag loads

    __shared__ float smA[2][BM * ASR];
    __shared__ float smB[2][BK * BSR];

    const int tid  = threadIdx.x;
    const int bm   = blockIdx.y * BM;
    const int bn   = blockIdx.x * BN;
    const int warp = tid >> 5;
    const int lane = tid & 31;
    const int wm   = warp & 3;   // 4 warps along M (32 rows each)
    const int wn   = warp >> 2;  // 2 warps along N (64 cols each)
    const int g    = lane >> 2;  // groupID 0..7
    const int t4   = lane & 3;   // threadID_in_group 0..3

    const uint32_t sA = (uint32_t)__cvta_generic_to_shared(&smA[0][0]);
    const uint32_t sB = (uint32_t)__cvta_generic_to_shared(&smB[0][0]);

    float acc[2][8][4] = {};

    auto load_stage = [&](int st, int k0) {
        const float* Ab = A + (size_t)bm * K + k0;
        #pragma unroll
        for (int p = 0; p < 2; p++) {
            int f = tid + p * 256;
            int row = f >> 2, c4 = (f & 3) << 2;
            cp16(sA + (uint32_t)((st * BM * ASR + row * ASR + c4) * 4),
                 Ab + (size_t)row * K + c4);
        }
        const float* Bb = B + (size_t)k0 * N + bn;
        #pragma unroll
        for (int p = 0; p < 2; p++) {
            int f = tid + p * 256;
            int row = f >> 5, c4 = (f & 31) << 2;
            cp16(sB + (uint32_t)((st * BK * BSR + row * BSR + c4) * 4),
                 Bb + (size_t)row * N + c4);
        }
        asm volatile("cp.async.commit_group;\n");
    };

    load_stage(0, 0);
    int stage = 0;

    for (int k0 = 0; k0 < K; k0 += BK) {
        asm volatile("cp.async.wait_group 0;\n");
        __syncthreads();
        if (k0 + BK < K) load_stage(stage ^ 1, k0 + BK);

        const float* cA = &smA[stage][0];
        const float* cB = &smB[stage][0];

        #pragma unroll
        for (int ks = 0; ks < 2; ks++) {
            const int kb = ks * 8;
            uint32_t ua[2][4], ub[8][2];
            #pragma unroll
            for (int mt = 0; mt < 2; mt++) {
                int r = wm * 32 + mt * 16 + g;
                ua[mt][0] = f2tf32(cA[(size_t)r       * ASR + kb + t4]);
                ua[mt][1] = f2tf32(cA[(size_t)(r + 8) * ASR + kb + t4]);
                ua[mt][2] = f2tf32(cA[(size_t)r       * ASR + kb + t4 + 4]);
                ua[mt][3] = f2tf32(cA[(size_t)(r + 8) * ASR + kb + t4 + 4]);
            }
            #pragma unroll
            for (int nt = 0; nt < 8; nt++) {
                int c = wn * 64 + nt * 8 + g;
                ub[nt][0] = f2tf32(cB[(size_t)(kb + t4)     * BSR + c]);
                ub[nt][1] = f2tf32(cB[(size_t)(kb + t4 + 4) * BSR + c]);
            }
            #pragma unroll
            for (int mt = 0; mt < 2; mt++)
                #pragma unroll
                for (int nt = 0; nt < 8; nt++)
                    asm volatile(
                        "mma.sync.aligned.m16n8k8.row.col.f32.tf32.tf32.f32 "
                        "{%0,%1,%2,%3}, {%4,%5,%6,%7}, {%8,%9}, {%0,%1,%2,%3};"
                        : "+f"(acc[mt][nt][0]), "+f"(acc[mt][nt][1]),
                          "+f"(acc[mt][nt][2]), "+f"(acc[mt][nt][3])
                        : "r"(ua[mt][0]), "r"(ua[mt][1]), "r"(ua[mt][2]), "r"(ua[mt][3]),
                          "r"(ub[nt][0]), "r"(ub[nt][1]));
        }
        stage ^= 1;
    }

    // Epilogue: bias add + store (float2 per fragment row)
    #pragma unroll
    for (int mt = 0; mt < 2; mt++) {
        #pragma unroll
        for (int nt = 0; nt < 8; nt++) {
            int r = bm + wm * 32 + mt * 16 + g;
            int c = bn + wn * 64 + nt * 8 + 2 * t4;
            float2 bv = *reinterpret_cast<const float2*>(bias + c);
            float2 o0 = make_float2(acc[mt][nt][0] + bv.x, acc[mt][nt][1] + bv.y);
            float2 o1 = make_float2(acc[mt][nt][2] + bv.x, acc[mt][nt][3] + bv.y);
            *reinterpret_cast<float2*>(C + (size_t)r * N + c)       = o0;
            *reinterpret_cast<float2*>(C + (size_t)(r + 8) * N + c) = o1;
        }
    }
}

// ---------------------------------------------------------------------------
// Mid kernel: RoPE(Q) -> gates u,v; kernels = silu(H1) @ kg_w2 + kg_b2
// ---------------------------------------------------------------------------
__global__ __launch_bounds__(256) void mid_kernel(
    const float* __restrict__ kg_w2, const float* __restrict__ kg_b2,
    const float* __restrict__ gate_w, const float* __restrict__ gate_b)
{
    __shared__ float h1s[16][RED];
    const int tid = threadIdx.x;
    const int tokBase = blockIdx.x * 16;

    for (int i = tid; i < 16 * RED; i += 256) {
        int tk = i / RED, c = i % RED;
        float val = g_H1[(size_t)(tokBase + tk) * RED + c];
        h1s[tk][c] = val / (1.f + expf(-val));
    }
    __syncthreads();

    const int tl = tid >> 4;
    const int h  = tid & 15;
    const int gtok = tokBase + tl;
    const int b = gtok >> 12;
    const int t = gtok & (SEQ - 1);

    float q[QK];
    const float4* qp = reinterpret_cast<const float4*>(g_Q + (size_t)gtok * HID + h * QK);
    #pragma unroll
    for (int j = 0; j < QK / 4; j++) {
        float4 f = qp[j];
        q[4*j] = f.x; q[4*j+1] = f.y; q[4*j+2] = f.z; q[4*j+3] = f.w;
    }

    const float LOGC = 9.210340371976184f / 16.0f;
    #pragma unroll
    for (int j = 0; j < 32; j++) {
        float freq = expf(-LOGC * (float)j);
        float s, c;
        sincosf((float)t * freq, &s, &c);
        float a = q[j], bq = q[j + 32];
        q[j]      = a * c - bq * s;
        q[j + 32] = a * s + bq * c;
    }

    float du = gate_b[0], dv = gate_b[1];
    #pragma unroll
    for (int j = 0; j < QK; j++) {
        du = fmaf(q[j], gate_w[2 * j],     du);
        dv = fmaf(q[j], gate_w[2 * j + 1], dv);
    }
    float uu = 1.f / (1.f + expf(-du));
    float vv = 1.f / (1.f + expf(-dv));

    const size_t bhT = ((size_t)b * NH + h) * SEQ + t;
    g_u[bhT] = uu;
    g_v[bhT] = vv;

    float ak[KS];
    #pragma unroll
    for (int k = 0; k < KS; k++) ak[k] = kg_b2[h * KS + k];
    for (int r = 0; r < RED; r++) {
        float hv = h1s[tl][r];
        float4 w = *reinterpret_cast<const float4*>(kg_w2 + (size_t)r * (NH * KS) + h * KS);
        ak[0] = fmaf(hv, w.x, ak[0]);
        ak[1] = fmaf(hv, w.y, ak[1]);
        ak[2] = fmaf(hv, w.z, ak[2]);
        ak[3] = fmaf(hv, w.w, ak[3]);
    }
    #pragma unroll
    for (int k = 0; k < KS; k++) g_k4[bhT * KS + k] = ak[k];
}

// ---------------------------------------------------------------------------
// Scan kernel: one block per (b, h), 64 threads (d).
// ---------------------------------------------------------------------------
__global__ __launch_bounds__(64) void scan_kernel()
{
    const int bh = blockIdx.x;
    const int b  = bh / NH;
    const int h  = bh % NH;
    const int d  = threadIdx.x;

    const float* up = g_u  + (size_t)bh * SEQ;
    const float* vp = g_v  + (size_t)bh * SEQ;
    const float* kp = g_k4 + (size_t)bh * SEQ * KS;

    const size_t base = ((size_t)b * SEQ * NH + h) * VD + d;
    const float* Vp = g_V    + base;
    float*       Op = g_scan + base;
    constexpr int STR = NH * VD;

    __shared__ float su[128], sv[128], sk[128 * KS];

    float ctx = 0.f, r0 = 0.f, r1 = 0.f, r2 = 0.f;

    for (int t0 = 0; t0 < SEQ; t0 += 128) {
        __syncthreads();
        for (int i = d; i < 128; i += 64) { su[i] = up[t0 + i]; sv[i] = vp[t0 + i]; }
        for (int i = d; i < 128 * KS; i += 64) sk[i] = kp[(size_t)t0 * KS + i];
        __syncthreads();

        #pragma unroll 4
        for (int i = 0; i < 128; i++) {
            float cur = Vp[(size_t)(t0 + i) * STR];
            float vm = fmaf(sk[4*i], r0,
                       fmaf(sk[4*i+1], r1,
                       fmaf(sk[4*i+2], r2, sk[4*i+3] * cur)));
            ctx = fmaf(ctx, su[i], vm * sv[i]);
            Op[(size_t)(t0 + i) * STR] = ctx;
            r0 = r1; r1 = r2; r2 = cur;
        }
    }
}

// ---------------------------------------------------------------------------
// Launch
// ---------------------------------------------------------------------------
extern "C" void kernel_launch(void* const* d_in, const int* in_sizes, int n_in,
                              void* d_out, int out_size)
{
    const float* x      = (const float*)d_in[0];
    const float* W_q    = (const float*)d_in[1];
    const float* b_q    = (const float*)d_in[2];
    // W_k / b_k (d_in[3..4]) are dead in the reference — skipped.
    const float* W_v    = (const float*)d_in[5];
    const float* b_v    = (const float*)d_in[6];
    const float* kg_w1  = (const float*)d_in[7];
    const float* kg_b1  = (const float*)d_in[8];
    const float* kg_w2  = (const float*)d_in[9];
    const float* kg_b2  = (const float*)d_in[10];
    const float* gate_w = (const float*)d_in[11];
    const float* gate_b = (const float*)d_in[12];
    const float* W_out  = (const float*)d_in[13];
    const float* b_out  = (const float*)d_in[14];
    float* out = (float*)d_out;

    static float *pQ = nullptr, *pV = nullptr, *pH1 = nullptr, *pScan = nullptr;
    if (!pQ) {
        cudaGetSymbolAddress((void**)&pQ,    g_Q);
        cudaGetSymbolAddress((void**)&pV,    g_V);
        cudaGetSymbolAddress((void**)&pH1,   g_H1);
        cudaGetSymbolAddress((void**)&pScan, g_scan);
    }

    dim3 blk(256);
    gemm_tf32<<<dim3(HID / 128, MTOK / 128), blk>>>(x, W_q, b_q, pQ, MTOK, HID, HID);
    gemm_tf32<<<dim3(HID / 128, MTOK / 128), blk>>>(x, W_v, b_v, pV, MTOK, HID, HID);
    gemm_tf32<<<dim3(RED / 128, MTOK / 128), blk>>>(x, kg_w1, kg_b1, pH1, MTOK, RED, HID);
    mid_kernel<<<MTOK / 16, 256>>>(kg_w2, kg_b2, gate_w, gate_b);
    scan_kernel<<<BATCH * NH, 64>>>();
    gemm_tf32<<<dim3(HID / 128, MTOK / 128), blk>>>(pScan, W_out, b_out, out, MTOK, HID, HID);
}